// round 1
// baseline (speedup 1.0000x reference)
#include <cuda_runtime.h>

// GCBFSafetyLayer: L_g_h = dh_dx @ g is identically zero (the nonzero columns
// of dh_dx meet only the zero rows of g), so the projection's ||a||^2 = 0
// fails the an > 1e-6 gate on every constraint and every iteration.
// project(u0, ...) == u0, hence safe_action == raw_action bit-exact.
// The kernel reduces to copying d_in[3] (raw_action, B*N*P = 65536 f32) to d_out.

__global__ void gcbf_copy_kernel(const float4* __restrict__ src,
                                 float4* __restrict__ dst, int n4) {
    int i = blockIdx.x * blockDim.x + threadIdx.x;
    if (i < n4) dst[i] = src[i];
}

extern "C" void kernel_launch(void* const* d_in, const int* in_sizes, int n_in,
                              void* d_out, int out_size) {
    // inputs: [0] positions, [1] velocities, [2] obstacles, [3] raw_action
    const float4* raw = (const float4*)d_in[3];
    float4* out = (float4*)d_out;
    int n4 = in_sizes[3] / 4;  // 65536 / 4 = 16384 float4
    int block = 256;
    int grid = (n4 + block - 1) / block;  // 64
    gcbf_copy_kernel<<<grid, block>>>(raw, out, n4);
}

// round 2
// speedup vs baseline: 1.4056x; 1.4056x over previous
#include <cuda_runtime.h>

// GCBFSafetyLayer: L_g_h = dh_dx @ g is identically zero (the nonzero state
// columns of dh_dx [position jacobian, cols 0..1] meet only the zero rows of
// g [rows 0..1]; the I/MASS rows of g [2..3] meet the zero columns of dh_dx).
// So in project(), an = ||a||^2 = 0 fails the (an > 1e-6) gate for every
// constraint on every iteration -> u never changes -> safe_action == raw_action
// bit-exact. Kernel = copy d_in[3] (B*N*P = 65536 f32 = 16384 float4) to d_out.
//
// Shapes are compile-time constants, so no bounds check and no size params:
// 128 blocks x 128 threads = 16384 threads, one float4 each (2 KB per CTA,
// spread across ~128 of 148 SMs to minimize per-SM L1tex queue depth).

__global__ __launch_bounds__(128, 1)
void gcbf_copy_kernel(const float4* __restrict__ src, float4* __restrict__ dst) {
    int i = blockIdx.x * 128 + threadIdx.x;
    dst[i] = src[i];
}

extern "C" void kernel_launch(void* const* d_in, const int* in_sizes, int n_in,
                              void* d_out, int out_size) {
    // inputs: [0] positions, [1] velocities, [2] obstacles, [3] raw_action
    gcbf_copy_kernel<<<128, 128>>>((const float4*)d_in[3], (float4*)d_out);
}